// round 5
// baseline (speedup 1.0000x reference)
#include <cuda_runtime.h>
#include <math.h>

#define UN 100000
#define INUM 50000
#define NN 150000
#define DD 64
#define EN 3000000
#define BN 8192
#define NEG_SLOPE_F 0.2f

// ---------------- scratch (no allocs allowed -> device globals) ----------------
__device__ int   g_cnt[NN];
__device__ int   g_fill[NN];
__device__ int   g_rowptr[NN + 1];
__device__ int   g_bsums[256];
__device__ int   g_ccol[EN];
__device__ float g_cval[EN];
__device__ float g_ego[NN * DD];    // current (unnormalized) embedding
__device__ float g_side[NN * DD];   // spmm output
__device__ float g_n1[NN * DD];     // normalized layer-1 embedding
__device__ float g_n2[NN * DD];     // normalized layer-2 embedding
__device__ float g_acc[2];          // [softplus sum, reg sum]

// ---------------- init: ego = concat(user_emb, item_emb); zero counters --------
__global__ void init_kernel(const float* __restrict__ ue, const float* __restrict__ ie) {
    int i = blockIdx.x * blockDim.x + threadIdx.x;
    if (i < NN * DD) g_ego[i] = (i < UN * DD) ? ue[i] : ie[i - UN * DD];
    if (i < NN) { g_cnt[i] = 0; g_fill[i] = 0; }
    if (i == 0) { g_acc[0] = 0.f; g_acc[1] = 0.f; }
}

// ---------------- CSR build ----------------------------------------------------
__global__ void hist_kernel(const int* __restrict__ rows) {
    int e = blockIdx.x * blockDim.x + threadIdx.x;
    if (e < EN) atomicAdd(&g_cnt[rows[e]], 1);
}

__global__ void scan_block_kernel() {
    __shared__ int s[1024];
    int tid = threadIdx.x;
    int i = blockIdx.x * 1024 + tid;
    int v = (i < NN) ? g_cnt[i] : 0;
    s[tid] = v;
    __syncthreads();
    for (int off = 1; off < 1024; off <<= 1) {
        int t = (tid >= off) ? s[tid - off] : 0;
        __syncthreads();
        s[tid] += t;
        __syncthreads();
    }
    if (i < NN) g_rowptr[i] = s[tid] - v;       // exclusive
    if (tid == 1023) g_bsums[blockIdx.x] = s[1023];
}

__global__ void scan_top_kernel() {
    int run = 0;
    const int nb = (NN + 1023) / 1024;
    for (int b = 0; b < nb; b++) {
        int t = g_bsums[b];
        g_bsums[b] = run;
        run += t;
    }
    g_rowptr[NN] = run;   // == EN
}

__global__ void scan_add_kernel() {
    int i = blockIdx.x * blockDim.x + threadIdx.x;
    if (i < NN) g_rowptr[i] += g_bsums[i >> 10];
}

__global__ void scatter_kernel(const int* __restrict__ rows, const int* __restrict__ cols,
                               const float* __restrict__ vals) {
    int e = blockIdx.x * blockDim.x + threadIdx.x;
    if (e < EN) {
        int r = rows[e];
        int p = g_rowptr[r] + atomicAdd(&g_fill[r], 1);
        g_ccol[p] = cols[e];
        g_cval[p] = vals[e];
    }
}

// ---------------- SpMM: warp per row, no atomics --------------------------------
__global__ void __launch_bounds__(256) spmm_kernel() {
    int w = (blockIdx.x * 256 + threadIdx.x) >> 5;
    int lane = threadIdx.x & 31;
    if (w >= NN) return;
    int s = g_rowptr[w], e = g_rowptr[w + 1];
    float a0 = 0.f, a1 = 0.f;
    for (int i = s; i < e; i++) {
        int c = __ldg(&g_ccol[i]);
        float v = __ldg(&g_cval[i]);
        const float* xr = g_ego + c * 64;
        a0 = fmaf(v, __ldg(xr + lane), a0);
        a1 = fmaf(v, __ldg(xr + lane + 32), a1);
    }
    g_side[w * 64 + lane] = a0;
    g_side[w * 64 + lane + 32] = a1;
}

// ---------------- fused dense: leaky(side@Wg+bg)@Wm+bm, normalize ---------------
// 4 rows per warp; W transposed in smem with stride 68 (conflict-free LDS.128).
__global__ void __launch_bounds__(256) dense_kernel(
    const float* __restrict__ Wg, const float* __restrict__ bg,
    const float* __restrict__ Wm, const float* __restrict__ bm,
    int layer)
{
    __shared__ float sWg[64 * 68];
    __shared__ float sWm[64 * 68];
    __shared__ float sbg[64], sbm[64];
    __shared__ float sxs[8 * 256];   // 8 warps * 4 rows * 64

    float* normOut = (layer == 0) ? g_n1 : g_n2;

    int tid = threadIdx.x;
    for (int i = tid; i < 64 * 64; i += 256) {
        int k = i >> 6, j = i & 63;
        sWg[j * 68 + k] = Wg[i];   // sWg[j][k] = Wg[k][j]
        sWm[j * 68 + k] = Wm[i];
    }
    if (tid < 64) { sbg[tid] = bg[tid]; sbm[tid] = bm[tid]; }
    __syncthreads();

    int warp = tid >> 5, lane = tid & 31;
    const float4* wga = reinterpret_cast<const float4*>(sWg + lane * 68);
    const float4* wgb = reinterpret_cast<const float4*>(sWg + (lane + 32) * 68);
    const float4* wma = reinterpret_cast<const float4*>(sWm + lane * 68);
    const float4* wmb = reinterpret_cast<const float4*>(sWm + (lane + 32) * 68);
    float* myx = sxs + warp * 256;
    const float4* x4 = reinterpret_cast<const float4*>(myx);
    float b0a = sbg[lane], b0b = sbg[lane + 32];
    float b1a = sbm[lane], b1b = sbm[lane + 32];

    const int ngroups = (NN + 3) >> 2;
    for (int grp = blockIdx.x * 8 + warp; grp < ngroups; grp += gridDim.x * 8) {
        int base = grp << 2;
        __syncwarp();
        #pragma unroll
        for (int r = 0; r < 4; r++) {
            int row = base + r;
            float v0 = 0.f, v1 = 0.f;
            if (row < NN) { v0 = g_side[row * 64 + lane]; v1 = g_side[row * 64 + lane + 32]; }
            myx[r * 64 + lane] = v0;
            myx[r * 64 + lane + 32] = v1;
        }
        __syncwarp();

        float a0[4], a1[4];
        #pragma unroll
        for (int r = 0; r < 4; r++) { a0[r] = b0a; a1[r] = b0b; }
        #pragma unroll
        for (int kk = 0; kk < 16; kk++) {
            float4 wa = wga[kk], wb = wgb[kk];
            #pragma unroll
            for (int r = 0; r < 4; r++) {
                float4 xv = x4[r * 16 + kk];
                a0[r] = fmaf(xv.x, wa.x, a0[r]); a0[r] = fmaf(xv.y, wa.y, a0[r]);
                a0[r] = fmaf(xv.z, wa.z, a0[r]); a0[r] = fmaf(xv.w, wa.w, a0[r]);
                a1[r] = fmaf(xv.x, wb.x, a1[r]); a1[r] = fmaf(xv.y, wb.y, a1[r]);
                a1[r] = fmaf(xv.z, wb.z, a1[r]); a1[r] = fmaf(xv.w, wb.w, a1[r]);
            }
        }
        // leaky relu -> store g back into smem row buffer
        __syncwarp();
        #pragma unroll
        for (int r = 0; r < 4; r++) {
            float gA = a0[r] > 0.f ? a0[r] : NEG_SLOPE_F * a0[r];
            float gB = a1[r] > 0.f ? a1[r] : NEG_SLOPE_F * a1[r];
            myx[r * 64 + lane] = gA;
            myx[r * 64 + lane + 32] = gB;
        }
        __syncwarp();

        #pragma unroll
        for (int r = 0; r < 4; r++) { a0[r] = b1a; a1[r] = b1b; }
        #pragma unroll
        for (int kk = 0; kk < 16; kk++) {
            float4 wa = wma[kk], wb = wmb[kk];
            #pragma unroll
            for (int r = 0; r < 4; r++) {
                float4 xv = x4[r * 16 + kk];
                a0[r] = fmaf(xv.x, wa.x, a0[r]); a0[r] = fmaf(xv.y, wa.y, a0[r]);
                a0[r] = fmaf(xv.z, wa.z, a0[r]); a0[r] = fmaf(xv.w, wa.w, a0[r]);
                a1[r] = fmaf(xv.x, wb.x, a1[r]); a1[r] = fmaf(xv.y, wb.y, a1[r]);
                a1[r] = fmaf(xv.z, wb.z, a1[r]); a1[r] = fmaf(xv.w, wb.w, a1[r]);
            }
        }
        // write new ego + normalized output
        #pragma unroll
        for (int r = 0; r < 4; r++) {
            int row = base + r;
            if (row < NN) {
                g_ego[row * 64 + lane] = a0[r];
                g_ego[row * 64 + lane + 32] = a1[r];
            }
            float ss = a0[r] * a0[r] + a1[r] * a1[r];
            #pragma unroll
            for (int off = 16; off > 0; off >>= 1)
                ss += __shfl_xor_sync(0xFFFFFFFFu, ss, off);
            float inv = 1.0f / fmaxf(sqrtf(ss), 1e-12f);
            if (row < NN) {
                normOut[row * 64 + lane] = a0[r] * inv;
                normOut[row * 64 + lane + 32] = a1[r] * inv;
            }
        }
    }
}

// ---------------- BPR + reg loss: warp per triplet -----------------------------
__global__ void __launch_bounds__(256) loss_kernel(
    const int* __restrict__ user, const int* __restrict__ pos, const int* __restrict__ neg,
    const float* __restrict__ ue, const float* __restrict__ ie)
{
    int w = (blockIdx.x * 256 + threadIdx.x) >> 5;
    int lane = threadIdx.x & 31;
    if (w >= BN) return;
    int uu = user[w], pp = pos[w], nn = neg[w];
    const float* u0 = ue + uu * 64;
    const float* p0 = ie + pp * 64;
    const float* n0 = ie + nn * 64;
    int un = uu * 64, pn = (UN + pp) * 64, nd = (UN + nn) * 64;
    float ps = 0.f, ns = 0.f, rg = 0.f;
    #pragma unroll
    for (int h = 0; h < 2; h++) {
        int l = lane + h * 32;
        float a = u0[l], b = p0[l], c = n0[l];
        ps += a * b; ns += a * c; rg += a * a + b * b + c * c;
        float a1 = g_n1[un + l], b1 = g_n1[pn + l], c1 = g_n1[nd + l];
        ps += a1 * b1; ns += a1 * c1;
        float a2 = g_n2[un + l], b2 = g_n2[pn + l], c2 = g_n2[nd + l];
        ps += a2 * b2; ns += a2 * c2;
    }
    #pragma unroll
    for (int off = 16; off > 0; off >>= 1) {
        ps += __shfl_xor_sync(0xFFFFFFFFu, ps, off);
        ns += __shfl_xor_sync(0xFFFFFFFFu, ns, off);
        rg += __shfl_xor_sync(0xFFFFFFFFu, rg, off);
    }
    if (lane == 0) {
        float x = ns - ps;
        float sp = fmaxf(x, 0.f) + log1pf(expf(-fabsf(x)));   // stable softplus
        atomicAdd(&g_acc[0], sp);
        atomicAdd(&g_acc[1], rg);
    }
}

__global__ void finalize_kernel(float* __restrict__ out) {
    out[0] = g_acc[0] * (1.0f / (float)BN);
    out[1] = g_acc[1] * (0.5f * 0.0001f / (float)BN);
}

// ---------------- launch -------------------------------------------------------
extern "C" void kernel_launch(void* const* d_in, const int* in_sizes, int n_in,
                              void* d_out, int out_size) {
    const int*   user = (const int*)d_in[0];
    const int*   pos  = (const int*)d_in[1];
    const int*   neg  = (const int*)d_in[2];
    const int*   rows = (const int*)d_in[3];
    const int*   cols = (const int*)d_in[4];
    const float* vals = (const float*)d_in[5];
    const float* ue   = (const float*)d_in[6];
    const float* ie   = (const float*)d_in[7];
    const float* Wg0  = (const float*)d_in[8];
    const float* bg0  = (const float*)d_in[9];
    const float* Wm0  = (const float*)d_in[10];
    const float* bm0  = (const float*)d_in[11];
    const float* Wg1  = (const float*)d_in[12];
    const float* bg1  = (const float*)d_in[13];
    const float* Wm1  = (const float*)d_in[14];
    const float* bm1  = (const float*)d_in[15];
    float* out = (float*)d_out;

    init_kernel<<<(NN * DD + 255) / 256, 256>>>(ue, ie);

    // CSR build
    hist_kernel<<<(EN + 255) / 256, 256>>>(rows);
    scan_block_kernel<<<(NN + 1023) / 1024, 1024>>>();
    scan_top_kernel<<<1, 1>>>();
    scan_add_kernel<<<(NN + 255) / 256, 256>>>();
    scatter_kernel<<<(EN + 255) / 256, 256>>>(rows, cols, vals);

    // layer 0
    spmm_kernel<<<(NN * 32 + 255) / 256, 256>>>();
    dense_kernel<<<2344, 256>>>(Wg0, bg0, Wm0, bm0, 0);
    // layer 1
    spmm_kernel<<<(NN * 32 + 255) / 256, 256>>>();
    dense_kernel<<<2344, 256>>>(Wg1, bg1, Wm1, bm1, 1);

    // loss
    loss_kernel<<<(BN * 32 + 255) / 256, 256>>>(user, pos, neg, ue, ie);
    finalize_kernel<<<1, 1>>>(out);
}

// round 6
// speedup vs baseline: 1.0145x; 1.0145x over previous
#include <cuda_runtime.h>
#include <cuda_bf16.h>
#include <math.h>

#define UN 100000
#define NN 150000
#define DD 64
#define EN 3000000
#define BN 8192
#define NEG_SLOPE_F 0.2f

// ---------------- scratch (no allocs allowed -> device globals) ----------------
__device__ int   g_cnt[NN];
__device__ int   g_fill[NN];
__device__ int   g_rowptr[NN + 1];
__device__ int   g_bsums[256];
__device__ int2  g_edge[EN];                 // (col, float-bits val)
__device__ __nv_bfloat16 g_egoh[NN * DD];    // bf16 copy of current embedding (spmm gather source)
__device__ float g_side[NN * DD];            // spmm output
__device__ float g_n1[NN * DD];              // normalized layer-1 embedding
__device__ float g_n2[NN * DD];              // normalized layer-2 embedding
__device__ float g_acc[2];                   // [softplus sum, reg sum]

union U2 { unsigned long long u; float2 f; };

__device__ __forceinline__ void fma2(unsigned long long& d, unsigned long long a, unsigned long long b) {
    asm("fma.rn.f32x2 %0, %1, %2, %0;" : "+l"(d) : "l"(a), "l"(b));
}

// ---------------- init ---------------------------------------------------------
__global__ void init_kernel(const float* __restrict__ ue, const float* __restrict__ ie) {
    int i = blockIdx.x * blockDim.x + threadIdx.x;
    if (i < NN * DD) {
        float v = (i < UN * DD) ? ue[i] : ie[i - UN * DD];
        g_egoh[i] = __float2bfloat16_rn(v);
    }
    if (i < NN) { g_cnt[i] = 0; g_fill[i] = 0; }
    if (i == 0) { g_acc[0] = 0.f; g_acc[1] = 0.f; }
}

// ---------------- CSR build ----------------------------------------------------
__global__ void hist_kernel(const int* __restrict__ rows) {
    int e = blockIdx.x * blockDim.x + threadIdx.x;
    if (e < EN) atomicAdd(&g_cnt[rows[e]], 1);
}

__global__ void scan_block_kernel() {
    __shared__ int s[1024];
    int tid = threadIdx.x;
    int i = blockIdx.x * 1024 + tid;
    int v = (i < NN) ? g_cnt[i] : 0;
    s[tid] = v;
    __syncthreads();
    for (int off = 1; off < 1024; off <<= 1) {
        int t = (tid >= off) ? s[tid - off] : 0;
        __syncthreads();
        s[tid] += t;
        __syncthreads();
    }
    if (i < NN) g_rowptr[i] = s[tid] - v;       // exclusive
    if (tid == 1023) g_bsums[blockIdx.x] = s[1023];
}

// parallel top-level scan over the (NN+1023)/1024 = 147 block sums
__global__ void scan_top_kernel() {
    __shared__ int s[256];
    int tid = threadIdx.x;
    const int nb = (NN + 1023) / 1024;
    int v = (tid < nb) ? g_bsums[tid] : 0;
    s[tid] = v;
    __syncthreads();
    for (int off = 1; off < 256; off <<= 1) {
        int t = (tid >= off) ? s[tid - off] : 0;
        __syncthreads();
        s[tid] += t;
        __syncthreads();
    }
    if (tid < nb) g_bsums[tid] = s[tid] - v;    // exclusive
    if (tid == nb - 1) g_rowptr[NN] = s[tid];   // total == EN
}

__global__ void scan_add_kernel() {
    int i = blockIdx.x * blockDim.x + threadIdx.x;
    if (i < NN) g_rowptr[i] += g_bsums[i >> 10];
}

__global__ void scatter_kernel(const int* __restrict__ rows, const int* __restrict__ cols,
                               const float* __restrict__ vals) {
    int e = blockIdx.x * blockDim.x + threadIdx.x;
    if (e < EN) {
        int r = rows[e];
        int p = g_rowptr[r] + atomicAdd(&g_fill[r], 1);
        g_edge[p] = make_int2(cols[e], __float_as_int(vals[e]));
    }
}

// ---------------- SpMM: warp per row, bf16 gather, no atomics -------------------
__global__ void __launch_bounds__(256) spmm_kernel() {
    int w = (blockIdx.x * 256 + threadIdx.x) >> 5;
    int lane = threadIdx.x & 31;
    if (w >= NN) return;
    int s = g_rowptr[w], e = g_rowptr[w + 1];
    float a0 = 0.f, a1 = 0.f;
    int i = s;
    for (; i + 1 < e; i += 2) {
        int2 e0 = __ldg(&g_edge[i]);
        int2 e1 = __ldg(&g_edge[i + 1]);
        float v0 = __int_as_float(e0.y), v1 = __int_as_float(e1.y);
        __nv_bfloat162 h0 = __ldg((const __nv_bfloat162*)(g_egoh + e0.x * 64) + lane);
        __nv_bfloat162 h1 = __ldg((const __nv_bfloat162*)(g_egoh + e1.x * 64) + lane);
        float2 f0 = __bfloat1622float2(h0);
        float2 f1 = __bfloat1622float2(h1);
        a0 = fmaf(v0, f0.x, a0); a1 = fmaf(v0, f0.y, a1);
        a0 = fmaf(v1, f1.x, a0); a1 = fmaf(v1, f1.y, a1);
    }
    if (i < e) {
        int2 e0 = __ldg(&g_edge[i]);
        float v0 = __int_as_float(e0.y);
        __nv_bfloat162 h0 = __ldg((const __nv_bfloat162*)(g_egoh + e0.x * 64) + lane);
        float2 f0 = __bfloat1622float2(h0);
        a0 = fmaf(v0, f0.x, a0); a1 = fmaf(v0, f0.y, a1);
    }
    // lane handles dims (2*lane, 2*lane+1)
    ((float2*)(g_side + w * 64))[lane] = make_float2(a0, a1);
}

// ---------------- fused dense with packed f32x2 FMA -----------------------------
// 8 rows per warp. Weights pre-packed in smem as (W[k][j], W[k][j+32]) pairs;
// x pre-duplicated as (v,v) pairs -> fma.rn.f32x2 with zero runtime packing.
#define W_STRIDE 33                               // ulonglong2 units, +1 pad (conflict-free LDS.128)
#define OFF_WM  (32 * W_STRIDE * 16)              // 16896
#define OFF_BG  (2 * 32 * W_STRIDE * 16)          // 33792
#define OFF_BM  (OFF_BG + 256)
#define OFF_X   (OFF_BM + 256)
#define DSMEM   (OFF_X + 8 * 8 * 32 * 16)         // 67072 bytes

__global__ void __launch_bounds__(256) dense_kernel(
    const float* __restrict__ Wg, const float* __restrict__ bg,
    const float* __restrict__ Wm, const float* __restrict__ bm,
    int layer)
{
    extern __shared__ char sm[];
    float* normOut = (layer == 0) ? g_n1 : g_n2;
    int tid = threadIdx.x;

    // pack weights: sW[j][kk] = float4(W[2kk][j], W[2kk][j+32], W[2kk+1][j], W[2kk+1][j+32])
    {
        float* wgf = (float*)(sm);
        float* wmf = (float*)(sm + OFF_WM);
        for (int i = tid; i < 4096; i += 256) {
            int c = i & 3, kk = (i >> 2) & 31, jj = i >> 7;
            int k = 2 * kk + (c >> 1), col = jj + (c & 1) * 32;
            wgf[(jj * W_STRIDE + kk) * 4 + c] = Wg[k * 64 + col];
            wmf[(jj * W_STRIDE + kk) * 4 + c] = Wm[k * 64 + col];
        }
        if (tid < 32) {
            ((float2*)(sm + OFF_BG))[tid] = make_float2(bg[tid], bg[tid + 32]);
            ((float2*)(sm + OFF_BM))[tid] = make_float2(bm[tid], bm[tid + 32]);
        }
    }
    __syncthreads();

    int warp = tid >> 5, lane = tid & 31;
    const ulonglong2* wgp = (const ulonglong2*)(sm) + lane * W_STRIDE;
    const ulonglong2* wmp = (const ulonglong2*)(sm + OFF_WM) + lane * W_STRIDE;
    unsigned long long bgp = ((const unsigned long long*)(sm + OFF_BG))[lane];
    unsigned long long bmp = ((const unsigned long long*)(sm + OFF_BM))[lane];
    ulonglong2* xr = (ulonglong2*)(sm + OFF_X) + warp * 256;   // [8 rows][32 kk]
    float2* xw = (float2*)xr;                                   // (r*32 + k/2)*2 + (k&1)
    const int l2 = lane + 32;

    const int ngroups = (NN + 7) >> 3;
    for (int grp = blockIdx.x * 8 + warp; grp < ngroups; grp += gridDim.x * 8) {
        int base = grp << 3;
        __syncwarp();
        #pragma unroll
        for (int r = 0; r < 8; r++) {
            int row = base + r;
            float v0 = 0.f, v1 = 0.f;
            if (row < NN) { v0 = g_side[row * 64 + lane]; v1 = g_side[row * 64 + l2]; }
            xw[(r * 32 + (lane >> 1)) * 2 + (lane & 1)] = make_float2(v0, v0);
            xw[(r * 32 + (l2 >> 1)) * 2 + (l2 & 1)]     = make_float2(v1, v1);
        }
        __syncwarp();

        unsigned long long acc[8];
        #pragma unroll
        for (int r = 0; r < 8; r++) acc[r] = bgp;
        #pragma unroll 4
        for (int kk = 0; kk < 32; kk++) {
            ulonglong2 w2 = wgp[kk];
            #pragma unroll
            for (int r = 0; r < 8; r++) {
                ulonglong2 xv = xr[r * 32 + kk];
                fma2(acc[r], xv.x, w2.x);
                fma2(acc[r], xv.y, w2.y);
            }
        }

        // leaky relu -> write duplicated g back into x buffer
        __syncwarp();
        #pragma unroll
        for (int r = 0; r < 8; r++) {
            U2 u; u.u = acc[r];
            float gA = u.f.x > 0.f ? u.f.x : NEG_SLOPE_F * u.f.x;
            float gB = u.f.y > 0.f ? u.f.y : NEG_SLOPE_F * u.f.y;
            xw[(r * 32 + (lane >> 1)) * 2 + (lane & 1)] = make_float2(gA, gA);
            xw[(r * 32 + (l2 >> 1)) * 2 + (l2 & 1)]     = make_float2(gB, gB);
        }
        __syncwarp();

        #pragma unroll
        for (int r = 0; r < 8; r++) acc[r] = bmp;
        #pragma unroll 4
        for (int kk = 0; kk < 32; kk++) {
            ulonglong2 w2 = wmp[kk];
            #pragma unroll
            for (int r = 0; r < 8; r++) {
                ulonglong2 xv = xr[r * 32 + kk];
                fma2(acc[r], xv.x, w2.x);
                fma2(acc[r], xv.y, w2.y);
            }
        }

        // epilogue: new ego (bf16, only needed after layer 0) + normalized output
        #pragma unroll
        for (int r = 0; r < 8; r++) {
            U2 u; u.u = acc[r];
            float ss = u.f.x * u.f.x + u.f.y * u.f.y;
            #pragma unroll
            for (int off = 16; off > 0; off >>= 1)
                ss += __shfl_xor_sync(0xFFFFFFFFu, ss, off);
            float inv = 1.0f / fmaxf(sqrtf(ss), 1e-12f);
            int row = base + r;
            if (row < NN) {
                normOut[row * 64 + lane] = u.f.x * inv;
                normOut[row * 64 + l2]   = u.f.y * inv;
                if (layer == 0) {
                    g_egoh[row * 64 + lane] = __float2bfloat16_rn(u.f.x);
                    g_egoh[row * 64 + l2]   = __float2bfloat16_rn(u.f.y);
                }
            }
        }
    }
}

// ---------------- BPR + reg loss: warp per triplet -----------------------------
__global__ void __launch_bounds__(256) loss_kernel(
    const int* __restrict__ user, const int* __restrict__ pos, const int* __restrict__ neg,
    const float* __restrict__ ue, const float* __restrict__ ie)
{
    int w = (blockIdx.x * 256 + threadIdx.x) >> 5;
    int lane = threadIdx.x & 31;
    if (w >= BN) return;
    int uu = user[w], pp = pos[w], nn = neg[w];
    const float* u0 = ue + uu * 64;
    const float* p0 = ie + pp * 64;
    const float* n0 = ie + nn * 64;
    int un = uu * 64, pn = (UN + pp) * 64, nd = (UN + nn) * 64;
    float ps = 0.f, ns = 0.f, rg = 0.f;
    #pragma unroll
    for (int h = 0; h < 2; h++) {
        int l = lane + h * 32;
        float a = u0[l], b = p0[l], c = n0[l];
        ps += a * b; ns += a * c; rg += a * a + b * b + c * c;
        float a1 = g_n1[un + l], b1 = g_n1[pn + l], c1 = g_n1[nd + l];
        ps += a1 * b1; ns += a1 * c1;
        float a2 = g_n2[un + l], b2 = g_n2[pn + l], c2 = g_n2[nd + l];
        ps += a2 * b2; ns += a2 * c2;
    }
    #pragma unroll
    for (int off = 16; off > 0; off >>= 1) {
        ps += __shfl_xor_sync(0xFFFFFFFFu, ps, off);
        ns += __shfl_xor_sync(0xFFFFFFFFu, ns, off);
        rg += __shfl_xor_sync(0xFFFFFFFFu, rg, off);
    }
    if (lane == 0) {
        float x = ns - ps;
        float sp = fmaxf(x, 0.f) + log1pf(expf(-fabsf(x)));   // stable softplus
        atomicAdd(&g_acc[0], sp);
        atomicAdd(&g_acc[1], rg);
    }
}

__global__ void finalize_kernel(float* __restrict__ out) {
    out[0] = g_acc[0] * (1.0f / (float)BN);
    out[1] = g_acc[1] * (0.5f * 0.0001f / (float)BN);
}

// ---------------- launch -------------------------------------------------------
extern "C" void kernel_launch(void* const* d_in, const int* in_sizes, int n_in,
                              void* d_out, int out_size) {
    const int*   user = (const int*)d_in[0];
    const int*   pos  = (const int*)d_in[1];
    const int*   neg  = (const int*)d_in[2];
    const int*   rows = (const int*)d_in[3];
    const int*   cols = (const int*)d_in[4];
    const float* vals = (const float*)d_in[5];
    const float* ue   = (const float*)d_in[6];
    const float* ie   = (const float*)d_in[7];
    const float* Wg0  = (const float*)d_in[8];
    const float* bg0  = (const float*)d_in[9];
    const float* Wm0  = (const float*)d_in[10];
    const float* bm0  = (const float*)d_in[11];
    const float* Wg1  = (const float*)d_in[12];
    const float* bg1  = (const float*)d_in[13];
    const float* Wm1  = (const float*)d_in[14];
    const float* bm1  = (const float*)d_in[15];
    float* out = (float*)d_out;

    cudaFuncSetAttribute(dense_kernel, cudaFuncAttributeMaxDynamicSharedMemorySize, DSMEM);

    init_kernel<<<(NN * DD + 255) / 256, 256>>>(ue, ie);

    // CSR build
    hist_kernel<<<(EN + 255) / 256, 256>>>(rows);
    scan_block_kernel<<<(NN + 1023) / 1024, 1024>>>();
    scan_top_kernel<<<1, 256>>>();
    scan_add_kernel<<<(NN + 255) / 256, 256>>>();
    scatter_kernel<<<(EN + 255) / 256, 256>>>(rows, cols, vals);

    // layer 0
    spmm_kernel<<<(NN * 32 + 255) / 256, 256>>>();
    dense_kernel<<<444, 256, DSMEM>>>(Wg0, bg0, Wm0, bm0, 0);
    // layer 1
    spmm_kernel<<<(NN * 32 + 255) / 256, 256>>>();
    dense_kernel<<<444, 256, DSMEM>>>(Wg1, bg1, Wm1, bm1, 1);

    // loss
    loss_kernel<<<(BN * 32 + 255) / 256, 256>>>(user, pos, neg, ue, ie);
    finalize_kernel<<<1, 1>>>(out);
}